// round 3
// baseline (speedup 1.0000x reference)
#include <cuda_runtime.h>

// out[i, h=n*7+o, m] = sum_{j<48,k<3} W[i,j,k] * x[j, n*7+(o+k-1), m]
//   (term dropped when o+k-1 outside [0,7))
// x: (48,56,56) f32   W: (192,48,3) f32   out: (192,56,56) f32

#define JCH 48
#define KTAP 3
#define MW 56
#define MP 64            // padded m (float4-friendly)
#define BI 16            // output channels per block
#define WSS 18           // ws row stride: even (8B-aligned f2) + conflict-light scatter
#define NTHREADS 128

__global__ __launch_bounds__(NTHREADS)
void fold_conv_kernel(const float* __restrict__ x,
                      const float* __restrict__ W,
                      float* __restrict__ out)
{
    extern __shared__ float sm[];
    float* xs = sm;                         // [KTAP*JCH][MP]  = 144*64 floats (36 KB)
    float* ws = sm + KTAP * JCH * MP;       // [JCH*KTAP][WSS] = 144*18 floats (10 KB)

    const int tid = threadIdx.x;
    const int h  = blockIdx.x;              // 0..55
    const int n  = h / 7;
    const int o  = h - n * 7;
    const int i0 = blockIdx.y * BI;         // 0..176 step 16

    // ---- load x slab: 144 rows x 16 float4, coalesced, zero-padded ----
    {
        float4* xs4 = (float4*)xs;
        #pragma unroll
        for (int it = 0; it < (KTAP * JCH * 16) / NTHREADS; ++it) {
            int idx = tid + it * NTHREADS;          // 0..2303
            int row = idx >> 4;                     // k*48+j
            int s   = idx & 15;                     // float4 slot
            int k   = row / JCH;
            int j   = row - k * JCH;
            int r   = o + k - 1;
            float4 v = make_float4(0.f, 0.f, 0.f, 0.f);
            if (r >= 0 && r < 7 && s < 14)
                v = *(const float4*)&x[(j * 56 + n * 7 + r) * 56 + s * 4];
            xs4[idx] = v;
        }
    }
    // ---- load W tile transposed: [jk][ii], coalesced gmem read ----
    #pragma unroll
    for (int it = 0; it < (BI * JCH * KTAP) / NTHREADS; ++it) {
        int idx = tid + it * NTHREADS;              // 0..2303
        int ii  = idx / (JCH * KTAP);
        int jk  = idx - ii * (JCH * KTAP);
        ws[jk * WSS + ii] = W[(i0 + ii) * (JCH * KTAP) + jk];
    }
    __syncthreads();

    // ---- register-tiled mainloop: each thread computes 2i x 4m ----
    const int mg  = tid & 15;               // m fastest -> coalesced stores
    const int ig  = tid >> 4;               // 8 i-groups
    const int m0  = mg * 4;                 // mg 14,15 hit padding (discarded)
    const int ii0 = ig * 2;

    float acc[2][4];
    #pragma unroll
    for (int a = 0; a < 2; ++a)
        #pragma unroll
        for (int b = 0; b < 4; ++b)
            acc[a][b] = 0.0f;

    #pragma unroll 4
    for (int j = 0; j < JCH; ++j) {
        float4 xv[KTAP];
        float2 wv[KTAP];
        #pragma unroll
        for (int k = 0; k < KTAP; ++k) {
            xv[k] = *(const float4*)&xs[(k * JCH + j) * MP + m0];
            wv[k] = *(const float2*)&ws[(j * 3 + k) * WSS + ii0];
        }
        #pragma unroll
        for (int k = 0; k < KTAP; ++k) {
            acc[0][0] = fmaf(wv[k].x, xv[k].x, acc[0][0]);
            acc[0][1] = fmaf(wv[k].x, xv[k].y, acc[0][1]);
            acc[0][2] = fmaf(wv[k].x, xv[k].z, acc[0][2]);
            acc[0][3] = fmaf(wv[k].x, xv[k].w, acc[0][3]);
            acc[1][0] = fmaf(wv[k].y, xv[k].x, acc[1][0]);
            acc[1][1] = fmaf(wv[k].y, xv[k].y, acc[1][1]);
            acc[1][2] = fmaf(wv[k].y, xv[k].z, acc[1][2]);
            acc[1][3] = fmaf(wv[k].y, xv[k].w, acc[1][3]);
        }
    }

    // ---- store (skip padded m-groups; 16B-aligned float4) ----
    if (m0 < MW) {
        #pragma unroll
        for (int a = 0; a < 2; ++a) {
            const int i = i0 + ii0 + a;
            float4 v = {acc[a][0], acc[a][1], acc[a][2], acc[a][3]};
            *(float4*)&out[(i * 56 + h) * 56 + m0] = v;
        }
    }
}

extern "C" void kernel_launch(void* const* d_in, const int* in_sizes, int n_in,
                              void* d_out, int out_size)
{
    const float* x = (const float*)d_in[0];   // 48*56*56
    const float* W = (const float*)d_in[1];   // 192*48*3
    float* out = (float*)d_out;               // 192*56*56

    const int smem = (KTAP * JCH * MP + JCH * KTAP * WSS) * (int)sizeof(float); // 47232 B
    static bool attr_set = false;
    if (!attr_set) {
        cudaFuncSetAttribute(fold_conv_kernel,
                             cudaFuncAttributeMaxDynamicSharedMemorySize, smem);
        attr_set = true;
    }
    dim3 grid(56, 12);
    fold_conv_kernel<<<grid, NTHREADS, smem>>>(x, W, out);
}

// round 4
// speedup vs baseline: 1.0308x; 1.0308x over previous
#include <cuda_runtime.h>

// out[i, h=n*7+o, m] = sum_{j<48,k<3} W[i,j,k] * x[j, n*7+(o+k-1), m]
//   (term dropped when o+k-1 outside [0,7))
// x: (48,56,56) f32   W: (192,48,3) f32   out: (192,56,56) f32

#define JCH 48
#define KTAP 3
#define MW 56
#define MP 64            // padded m (float4-friendly)
#define BI 32            // output channels per block
#define WSS 34           // ws row stride (even -> 8B-aligned float2 loads)
#define NTHREADS 256

__global__ __launch_bounds__(NTHREADS)
void fold_conv_kernel(const float* __restrict__ x,
                      const float* __restrict__ W,
                      float* __restrict__ out)
{
    extern __shared__ float sm[];
    float* xs = sm;                         // [KTAP*JCH][MP]  = 144*64 floats (36 KB)
    float* ws = sm + KTAP * JCH * MP;       // [JCH*KTAP][WSS] = 144*34 floats (19 KB)

    const int tid = threadIdx.x;
    const int h  = blockIdx.x;              // 0..55
    const int n  = h / 7;
    const int o  = h - n * 7;
    const int i0 = blockIdx.y * BI;         // 0..160 step 32

    // ---- load x slab: 144 rows x 16 float4, coalesced, zero-padded ----
    {
        float4* xs4 = (float4*)xs;
        #pragma unroll
        for (int it = 0; it < (KTAP * JCH * 16) / NTHREADS; ++it) {
            int idx = tid + it * NTHREADS;          // 0..2303
            int row = idx >> 4;                     // k*48+j
            int s   = idx & 15;                     // float4 slot
            int k   = row / JCH;
            int j   = row - k * JCH;
            int r   = o + k - 1;
            float4 v = make_float4(0.f, 0.f, 0.f, 0.f);
            if (r >= 0 && r < 7 && s < 14)
                v = *(const float4*)&x[(j * 56 + n * 7 + r) * 56 + s * 4];
            xs4[idx] = v;
        }
    }
    // ---- load W tile transposed [jk][ii]: coalesced gmem reads ----
    #pragma unroll
    for (int it = 0; it < (BI * JCH * KTAP) / NTHREADS; ++it) {
        int idx = tid + it * NTHREADS;              // 0..4607
        int ii  = idx / (JCH * KTAP);
        int jk  = idx - ii * (JCH * KTAP);
        ws[jk * WSS + ii] = W[(i0 + ii) * (JCH * KTAP) + jk];
    }
    __syncthreads();

    // ---- register-tiled mainloop: each thread computes 2i x 4m ----
    const int mg  = tid & 15;               // m fastest -> coalesced stores
    const int ig  = tid >> 4;               // 16 i-groups
    const int m0  = mg * 4;                 // mg 14,15 hit padding (discarded)
    const int ii0 = ig * 2;

    float acc[2][4];
    #pragma unroll
    for (int a = 0; a < 2; ++a)
        #pragma unroll
        for (int b = 0; b < 4; ++b)
            acc[a][b] = 0.0f;

    #pragma unroll 4
    for (int j = 0; j < JCH; ++j) {
        float4 xv[KTAP];
        float2 wv[KTAP];
        #pragma unroll
        for (int k = 0; k < KTAP; ++k) {
            xv[k] = *(const float4*)&xs[(k * JCH + j) * MP + m0];
            wv[k] = *(const float2*)&ws[(j * 3 + k) * WSS + ii0];
        }
        #pragma unroll
        for (int k = 0; k < KTAP; ++k) {
            acc[0][0] = fmaf(wv[k].x, xv[k].x, acc[0][0]);
            acc[0][1] = fmaf(wv[k].x, xv[k].y, acc[0][1]);
            acc[0][2] = fmaf(wv[k].x, xv[k].z, acc[0][2]);
            acc[0][3] = fmaf(wv[k].x, xv[k].w, acc[0][3]);
            acc[1][0] = fmaf(wv[k].y, xv[k].x, acc[1][0]);
            acc[1][1] = fmaf(wv[k].y, xv[k].y, acc[1][1]);
            acc[1][2] = fmaf(wv[k].y, xv[k].z, acc[1][2]);
            acc[1][3] = fmaf(wv[k].y, xv[k].w, acc[1][3]);
        }
    }

    // ---- store (skip padded m-groups; 16B-aligned float4) ----
    if (m0 < MW) {
        #pragma unroll
        for (int a = 0; a < 2; ++a) {
            const int i = i0 + ii0 + a;
            float4 v = {acc[a][0], acc[a][1], acc[a][2], acc[a][3]};
            *(float4*)&out[(i * 56 + h) * 56 + m0] = v;
        }
    }
}

extern "C" void kernel_launch(void* const* d_in, const int* in_sizes, int n_in,
                              void* d_out, int out_size)
{
    const float* x = (const float*)d_in[0];   // 48*56*56
    const float* W = (const float*)d_in[1];   // 192*48*3
    float* out = (float*)d_out;               // 192*56*56

    const int smem = (KTAP * JCH * MP + JCH * KTAP * WSS) * (int)sizeof(float); // 56448 B
    static bool attr_set = false;
    if (!attr_set) {
        cudaFuncSetAttribute(fold_conv_kernel,
                             cudaFuncAttributeMaxDynamicSharedMemorySize, smem);
        attr_set = true;
    }
    dim3 grid(56, 6);
    fold_conv_kernel<<<grid, NTHREADS, smem>>>(x, W, out);
}

// round 5
// speedup vs baseline: 1.3375x; 1.2975x over previous
#include <cuda_runtime.h>
#include <cstdint>

// out[i, h=n*7+o, m] = sum_{j<48,k<3} W[i,j,k] * x[j, n*7+(o+k-1), m]
//   (term dropped when o+k-1 outside [0,7))
// x: (48,56,56) f32   W: (192,48,3) f32   out: (192,56,56) f32
// Math done with packed fma.rn.f32x2 (2 fp32 MACs / instruction) over m-pairs.

#define JCH 48
#define KTAP 3
#define MW 56
#define MP 64            // padded m (float4-friendly)
#define BI 32            // output channels per block
#define WSS 36           // ws row stride, multiple of 4 -> 16B-aligned float4 loads
#define NTHREADS 128

// packed fp32x2 helpers (SASS FFMA2 path; ptxas never emits this from C++)
#define FMA_F32X2(d, a, b) \
    asm("fma.rn.f32x2 %0, %1, %2, %0;" : "+l"(d) : "l"(a), "l"(b))
#define PACK_DUP_F32X2(d, s) \
    asm("mov.b64 %0, {%1, %1};" : "=l"(d) : "r"(s))

__global__ __launch_bounds__(NTHREADS, 3)
void fold_conv_kernel(const float* __restrict__ x,
                      const float* __restrict__ W,
                      float* __restrict__ out)
{
    extern __shared__ float sm[];
    float* xs = sm;                         // [KTAP*JCH][MP]  = 144*64 floats (36 KB)
    float* ws = sm + KTAP * JCH * MP;       // [JCH*KTAP][WSS] = 144*36 floats (20.25 KB)

    const int tid = threadIdx.x;
    const int h  = blockIdx.x;              // 0..55
    const int n  = h / 7;
    const int o  = h - n * 7;
    const int i0 = blockIdx.y * BI;         // 0..160 step 32

    // ---- load x slab: 144 rows x 16 float4, coalesced, zero-padded ----
    {
        float4* xs4 = (float4*)xs;
        #pragma unroll
        for (int it = 0; it < (KTAP * JCH * 16) / NTHREADS; ++it) {
            int idx = tid + it * NTHREADS;          // 0..2303
            int row = idx >> 4;                     // k*48+j
            int s   = idx & 15;                     // float4 slot
            int k   = row / JCH;
            int j   = row - k * JCH;
            int r   = o + k - 1;
            float4 v = make_float4(0.f, 0.f, 0.f, 0.f);
            if (r >= 0 && r < 7 && s < 14)
                v = *(const float4*)&x[(j * 56 + n * 7 + r) * 56 + s * 4];
            xs4[idx] = v;
        }
    }
    // ---- load W tile transposed [jk][ii]: coalesced gmem reads ----
    #pragma unroll
    for (int it = 0; it < (BI * JCH * KTAP) / NTHREADS; ++it) {
        int idx = tid + it * NTHREADS;              // 0..4607
        int ii  = idx / (JCH * KTAP);
        int jk  = idx - ii * (JCH * KTAP);
        ws[jk * WSS + ii] = W[(i0 + ii) * (JCH * KTAP) + jk];
    }
    __syncthreads();

    // ---- register-tiled mainloop: each thread computes 4i x 4m (2 m-pairs) ----
    const int mg  = tid & 15;               // m fastest -> coalesced stores
    const int ig  = tid >> 4;               // 8 i-groups
    const int m0  = mg * 4;                 // mg 14,15 hit padding (discarded)
    const int ii0 = ig * 4;

    // acc[a][p]: output channel ii0+a, m-pair p (m0+2p, m0+2p+1)
    uint64_t acc[4][2];
    #pragma unroll
    for (int a = 0; a < 4; ++a) {
        acc[a][0] = 0ull;
        acc[a][1] = 0ull;
    }

    #pragma unroll 2
    for (int j = 0; j < JCH; ++j) {
        // x: 3 taps x 2 packed m-pairs (LDS.128 each, lanes already paired)
        ulonglong2 xv[KTAP];
        float4 wv[KTAP];
        #pragma unroll
        for (int k = 0; k < KTAP; ++k) {
            xv[k] = *(const ulonglong2*)&xs[(k * JCH + j) * MP + m0];
            wv[k] = *(const float4*)&ws[(j * 3 + k) * WSS + ii0];
        }
        #pragma unroll
        for (int k = 0; k < KTAP; ++k) {
            const float wr[4] = {wv[k].x, wv[k].y, wv[k].z, wv[k].w};
            #pragma unroll
            for (int a = 0; a < 4; ++a) {
                uint64_t wp;
                PACK_DUP_F32X2(wp, __float_as_uint(wr[a]));
                FMA_F32X2(acc[a][0], wp, xv[k].x);
                FMA_F32X2(acc[a][1], wp, xv[k].y);
            }
        }
    }

    // ---- store (skip padded m-groups; 16B-aligned) ----
    if (m0 < MW) {
        #pragma unroll
        for (int a = 0; a < 4; ++a) {
            const int i = i0 + ii0 + a;
            ulonglong2 v;
            v.x = acc[a][0];
            v.y = acc[a][1];
            *(ulonglong2*)&out[(i * 56 + h) * 56 + m0] = v;
        }
    }
}

extern "C" void kernel_launch(void* const* d_in, const int* in_sizes, int n_in,
                              void* d_out, int out_size)
{
    const float* x = (const float*)d_in[0];   // 48*56*56
    const float* W = (const float*)d_in[1];   // 192*48*3
    float* out = (float*)d_out;               // 192*56*56

    const int smem = (KTAP * JCH * MP + JCH * KTAP * WSS) * (int)sizeof(float); // 57600 B
    static bool attr_set = false;
    if (!attr_set) {
        cudaFuncSetAttribute(fold_conv_kernel,
                             cudaFuncAttributeMaxDynamicSharedMemorySize, smem);
        attr_set = true;
    }
    dim3 grid(56, 6);
    fold_conv_kernel<<<grid, NTHREADS, smem>>>(x, W, out);
}